// round 1
// baseline (speedup 1.0000x reference)
#include <cuda_runtime.h>

#define HID   768
#define NROWS 512          // B*S = 4*128
#define NPAIR 384          // HID/2

// Scratch (allocation-free rule: __device__ globals)
__device__ float g_rot[2][NROWS * HID];   // rotated review / reply
__device__ float g_proj[2][NROWS * HID];  // proj_review(+bias) / proj_reply

// ---- packed fp32x2 helpers (sm_100+ only; ptxas won't auto-fuse these) ----
__device__ __forceinline__ unsigned long long dup2(float a) {
    unsigned long long r;
    asm("mov.b64 %0, {%1, %1};" : "=l"(r) : "f"(a));
    return r;
}
__device__ __forceinline__ void fma2(unsigned long long& d,
                                     unsigned long long a,
                                     unsigned long long b) {
    asm("fma.rn.f32x2 %0, %1, %2, %0;" : "+l"(d) : "l"(a), "l"(b));
}

// ============================================================================
// 1) Rotary embedding for both inputs. Pair layout:
//    out[2i]   = x[2i]*cos_i - x[2i+1]*sin_i
//    out[2i+1] = x[2i+1]*cos_i + x[2i]*sin_i
// ============================================================================
__global__ void rotary_kernel(const float* __restrict__ rev,
                              const float* __restrict__ rep) {
    int idx = blockIdx.x * 256 + threadIdx.x;       // over 2*512*384 pairs
    if (idx >= 2 * NROWS * NPAIR) return;
    int which = idx / (NROWS * NPAIR);
    int rem   = idx - which * (NROWS * NPAIR);      // row*NPAIR + i
    int row   = rem / NPAIR;
    int i     = rem - row * NPAIR;
    int s     = row & 127;                          // position within sequence

    const float2* in = (const float2*)(which ? rep : rev);
    float2 x = in[rem];

    float inv = powf(10000.0f, (-2.0f * (float)i) / 768.0f);
    float ang = (float)s * inv;
    float c, sn;
    sincosf(ang, &sn, &c);

    float2 o;
    o.x = x.x * c - x.y * sn;
    o.y = x.y * c + x.x * sn;
    ((float2*)g_rot[which])[rem] = o;
}

// ============================================================================
// 2) GEMM: C[r][o] = sum_h A[r][h] * W[o][off + h]   (A = rotated input)
//    z = blockIdx.z selects (review, W[:, :H]) vs (reply, W[:, H:]).
//    64x64 tile, BK=16, 128 threads, 4x8 thread tile via packed fp32x2 FMA.
//    Bias folded into z==0 output so the epilogue is pure add+relu.
// ============================================================================
__global__ __launch_bounds__(128) void gemm_kernel(const float* __restrict__ W,
                                                   const float* __restrict__ bias) {
    __shared__ float As[16][66];   // [k][row], pad 66 -> conflict-free phases
    __shared__ float Bs[16][66];   // [k][o]

    int t = threadIdx.x;
    int z = blockIdx.z;
    int rowBase = blockIdx.y * 64;
    int oBase   = blockIdx.x * 64;
    const float* A = g_rot[z];
    float*       C = g_proj[z];
    int off = z * HID;             // column offset into W (0 or 768)

    unsigned long long acc[4][4];
    #pragma unroll
    for (int i = 0; i < 4; i++)
        #pragma unroll
        for (int p = 0; p < 4; p++) acc[i][p] = 0ull;   // (0.f, 0.f)

    int cx = t & 7, ry = t >> 3;
    int r0 = ry * 4, c0 = cx * 8;

    int lr = t >> 2;               // 0..31
    int kq = (t & 3) * 4;          // 0,4,8,12

    for (int k0 = 0; k0 < HID; k0 += 16) {
        #pragma unroll
        for (int c = 0; c < 2; c++) {
            int r = lr + c * 32;   // 0..63 : both A-row and W-row(o)
            float4 va = *(const float4*)&A[(rowBase + r) * HID + k0 + kq];
            As[kq + 0][r] = va.x; As[kq + 1][r] = va.y;
            As[kq + 2][r] = va.z; As[kq + 3][r] = va.w;
            float4 vw = *(const float4*)&W[(oBase + r) * 1536 + off + k0 + kq];
            Bs[kq + 0][r] = vw.x; Bs[kq + 1][r] = vw.y;
            Bs[kq + 2][r] = vw.z; Bs[kq + 3][r] = vw.w;
        }
        __syncthreads();

        #pragma unroll
        for (int kk = 0; kk < 16; kk++) {
            unsigned long long a2[4];
            #pragma unroll
            for (int i = 0; i < 4; i++) a2[i] = dup2(As[kk][r0 + i]);
            unsigned long long bp[4];
            #pragma unroll
            for (int p = 0; p < 4; p++) {
                float2 b2 = *(const float2*)&Bs[kk][c0 + 2 * p];
                bp[p] = *(unsigned long long*)&b2;
            }
            #pragma unroll
            for (int i = 0; i < 4; i++)
                #pragma unroll
                for (int p = 0; p < 4; p++)
                    fma2(acc[i][p], a2[i], bp[p]);
        }
        __syncthreads();
    }

    #pragma unroll
    for (int i = 0; i < 4; i++) {
        int row = rowBase + r0 + i;
        #pragma unroll
        for (int p = 0; p < 4; p++) {
            float2 v;
            asm("mov.b64 {%0, %1}, %2;" : "=f"(v.x), "=f"(v.y) : "l"(acc[i][p]));
            int col = oBase + c0 + 2 * p;
            if (z == 0) { v.x += bias[col]; v.y += bias[col + 1]; }
            *(float2*)&C[row * HID + col] = v;
        }
    }
}

// ============================================================================
// 3) Broadcast add + ReLU: out[b,n,m,:] = relu(pr[b,n,:] + pp[b,m,:])
//    8x8 (n x m) tile per block, 192 threads (one float4 column each).
//    Both proj tiles live in registers; 16 LDG.128 amortized over 64 STG.128.
//    HBM-write-bound: 201 MB of stores.
// ============================================================================
__global__ __launch_bounds__(192) void bcast_relu_kernel(float* __restrict__ out) {
    int t  = threadIdx.x;           // 0..191 : float4 column index
    int b  = blockIdx.z;
    int n0 = blockIdx.y * 8;
    int m0 = blockIdx.x * 8;

    const float4* PR = (const float4*)g_proj[0];
    const float4* PP = (const float4*)g_proj[1];

    float4 rv[8], pv[8];
    #pragma unroll
    for (int i = 0; i < 8; i++) rv[i] = PR[(b * 128 + n0 + i) * 192 + t];
    #pragma unroll
    for (int j = 0; j < 8; j++) pv[j] = PP[(b * 128 + m0 + j) * 192 + t];

    float4* O = (float4*)out;
    int base = ((b * 128 + n0) * 128 + m0) * 192 + t;

    #pragma unroll
    for (int i = 0; i < 8; i++) {
        #pragma unroll
        for (int j = 0; j < 8; j++) {
            float4 s;
            s.x = fmaxf(rv[i].x + pv[j].x, 0.0f);
            s.y = fmaxf(rv[i].y + pv[j].y, 0.0f);
            s.z = fmaxf(rv[i].z + pv[j].z, 0.0f);
            s.w = fmaxf(rv[i].w + pv[j].w, 0.0f);
            O[base + i * (128 * 192) + j * 192] = s;
        }
    }
}

// ============================================================================
// inputs (metadata order): review(4,128,768) reply(4,128,768) W(768,1536) b(768)
// output: float32 (4,128,128,768)
// ============================================================================
extern "C" void kernel_launch(void* const* d_in, const int* in_sizes, int n_in,
                              void* d_out, int out_size) {
    const float* review = (const float*)d_in[0];
    const float* reply  = (const float*)d_in[1];
    const float* W      = (const float*)d_in[2];
    const float* bias   = (const float*)d_in[3];
    float* out = (float*)d_out;

    rotary_kernel<<<1536, 256>>>(review, reply);
    gemm_kernel<<<dim3(12, 8, 2), 128>>>(W, bias);
    bcast_relu_kernel<<<dim3(16, 16, 4), 192>>>(out);
}